// round 12
// baseline (speedup 1.0000x reference)
#include <cuda_runtime.h>
#include <cstdint>

// stripe_post: m=2048, n=4096, m3=683, hX row-stride 4, GF r=49 eps=1
#define MM 2048
#define NN 4096
#define NG 1024             // float4 groups per row
#define M3 683
#define MN (MM * NN)
#define INVNORM (1.0f / 9604.0f)

#define CCH 32              // column-cumsum chunk rows
#define NCHB 64             // 2048/32
#define NCHD 22             // ceil(683/32)
#define VCH 64              // vertical box chunk rows (R5/R6 controlled pair: 64 > 32)
#define NVCH 32             // 2048/64

// skewed smem index: +1 float per 32 to spread banks (kills 4-way conflicts)
#define IDX(x) ((x) + ((x) >> 5))
#define CSZ (NN + 1 + ((NN + 1) >> 5) + 1)   // 4226

// scratch (static device arrays — allowed)
__device__ float4 g_CB[MN / 4];
__device__ float4 g_DC[(M3 * NN) / 4];
__device__ float4 g_CT[NCHB * NG];
__device__ float4 g_DT[NCHD * NG];
__device__ float4 g_OB[NCHB * NG];
__device__ float4 g_OD[NCHD * NG];
__device__ float4 g_BADPT[MN / 4];
__device__ float4 g_X[MN / 4];
__device__ float4 g_H1[MN / 4];
__device__ float4 g_H2[MN / 4];
__device__ float4 g_A[MN / 4];
__device__ float4 g_BB[MN / 4];
__device__ float4 g_PD[MN / 4];
__device__ float4 g_PT[NVCH * NG];
__device__ float4 g_OPD[NVCH * NG];

__device__ __forceinline__ float spf(float v) {
    return fmaxf(v, 0.0f) + __logf(1.0f + __expf(-fabsf(v)));
}
__device__ __forceinline__ float4 f4add(float4 a, float4 b) {
    return make_float4(a.x + b.x, a.y + b.y, a.z + b.z, a.w + b.w);
}
__device__ __forceinline__ float4 f4sub(float4 a, float4 b) {
    return make_float4(a.x - b.x, a.y - b.y, a.z - b.z, a.w - b.w);
}
__device__ __forceinline__ float4 f4mul(float4 a, float4 b) {
    return make_float4(a.x * b.x, a.y * b.y, a.z * b.z, a.w * b.w);
}
__device__ __forceinline__ float4 f4muls(float4 a, float s) {
    return make_float4(a.x * s, a.y * s, a.z * s, a.w * s);
}
__device__ __forceinline__ float4 f4zero() { return make_float4(0.f, 0.f, 0.f, 0.f); }
__device__ __forceinline__ float4 f4lerp(float4 a, float4 b, float t) {
    return make_float4(a.x + (b.x - a.x) * t, a.y + (b.y - a.y) * t,
                       a.z + (b.z - a.z) * t, a.w + (b.w - a.w) * t);
}
__device__ __forceinline__ float4 f4sp(float4 a) {
    return make_float4(spf(a.x), spf(a.y), spf(a.z), spf(a.w));
}

// --- K1: within-chunk column cumsum of a*softplus(wgt), float4 lanes ---
__global__ void k_colcumsum4(const float4* __restrict__ a, const float4* __restrict__ wgt,
                             float4* __restrict__ out, float4* __restrict__ tot, int rows) {
    int g = blockIdx.x * blockDim.x + threadIdx.x;
    int start = blockIdx.y * CCH;
    int end = start + CCH;
    if (end > rows) end = rows;
    float4 cum = f4zero();
    for (int i = start; i < end; i++) {
        float4 av = a[(size_t)i * NG + g];
        float4 wv = wgt[(size_t)i * NG + g];
        cum = f4add(cum, f4mul(av, f4sp(wv)));
        out[(size_t)i * NG + g] = cum;
    }
    tot[(size_t)blockIdx.y * NG + g] = cum;
}

// --- K2: PARALLEL exclusive scan of chunk totals across chunks ---
__global__ void k_scanpar(const float4* __restrict__ tot, float4* __restrict__ off, int nch) {
    __shared__ float4 htot[4];
    int c = threadIdx.x;         // 0..63
    int l = threadIdx.y;         // 0..3
    int g = blockIdx.x * 4 + l;
    float4 v = (c < nch) ? tot[(size_t)c * NG + g] : f4zero();
    float4 s = v;
    unsigned lane = c & 31;
#pragma unroll
    for (int o = 1; o < 32; o <<= 1) {
        float4 t;
        t.x = __shfl_up_sync(0xffffffffu, s.x, o);
        t.y = __shfl_up_sync(0xffffffffu, s.y, o);
        t.z = __shfl_up_sync(0xffffffffu, s.z, o);
        t.w = __shfl_up_sync(0xffffffffu, s.w, o);
        if (lane >= (unsigned)o) s = f4add(s, t);
    }
    if (c == 31) htot[l] = s;
    __syncthreads();
    float4 e = f4sub(s, v);
    if (c >= 32) e = f4add(e, htot[l]);
    if (c < nch) off[(size_t)c * NG + g] = e;
}

// --- K3: fusion (resize decay, b, b_adpt, x) — pure streaming, high MLP ---
__global__ void k_fusion4(const float4* __restrict__ fg, const float4* __restrict__ fm,
                          const float4* __restrict__ bold, const float4* __restrict__ hX,
                          const float4* __restrict__ recon, float4* __restrict__ out_b) {
    int t = blockIdx.x * blockDim.x + threadIdx.x;
    int i = t >> 10;
    int g = t & (NG - 1);
    float4 bcs = f4add(g_CB[t], g_OB[((i >> 5) << 10) + g]);
    float sf = (i + 0.5f) * (683.0f / 2048.0f) - 0.5f;
    sf = fminf(fmaxf(sf, 0.0f), 682.0f);
    int i0 = (int)sf;
    float fr = sf - (float)i0;
    int i1 = i0 + 1; if (i1 > 682) i1 = 682;
    float4 d0 = f4add(g_DC[(size_t)i0 * NG + g], g_OD[((i0 >> 5) << 10) + g]);
    float4 d1 = f4add(g_DC[(size_t)i1 * NG + g], g_OD[((i1 >> 5) << 10) + g]);
    float4 dec = f4lerp(d0, d1, fr);
    float4 fgv = fg[t], fmv = fm[t], bo = bold[t], rc = recon[t];
    float4 bf = make_float4(bcs.x + dec.x * (1.0f - fgv.x), bcs.y + dec.y * (1.0f - fgv.y),
                            bcs.z + dec.z * (1.0f - fgv.z), bcs.w + dec.w * (1.0f - fgv.w));
    float4 ba = make_float4(bf.x * fmv.x + bo.x * (1.0f - fmv.x),
                            bf.y * fmv.y + bo.y * (1.0f - fmv.y),
                            bf.z * fmv.z + bo.z * (1.0f - fmv.z),
                            bf.w * fmv.w + bo.w * (1.0f - fmv.w));
    float4 hx = hX[(size_t)(i * 4) * NG + g];
    out_b[t] = bf;
    g_BADPT[t] = ba;
    g_X[t] = f4sub(f4add(hx, ba), rc);
}

// --- K4/K6: horizontal box via unpadded float4 prefix scan + edge corrections ---
// window s in [j-48, j+49] clamped (replicate):
//  box[j] = P[min(j+50,N)] - P[max(j-48,0)] + max(0,48-j)*x0 + max(0,j-4046)*xN
// smem prefix arrays use skewed indexing IDX() for conflict-free access.
__global__ __launch_bounds__(1024) void k_hbox4(const float4* __restrict__ in1,
                                                const float4* __restrict__ in2,
                                                float4* __restrict__ out1,
                                                float4* __restrict__ out2,
                                                int useSquare) {
    __shared__ float c1[CSZ];
    __shared__ float c2[CSZ];
    __shared__ float w1[32], w2[32];
    const int row = blockIdx.x;
    const int tid = threadIdx.x;
    float4 v1 = in1[(size_t)row * NG + tid];
    float4 v2 = useSquare ? f4mul(v1, v1) : in2[(size_t)row * NG + tid];
    float l1[4], l2[4];
    l1[0] = v1.x; l1[1] = l1[0] + v1.y; l1[2] = l1[1] + v1.z; l1[3] = l1[2] + v1.w;
    l2[0] = v2.x; l2[1] = l2[0] + v2.y; l2[2] = l2[1] + v2.z; l2[3] = l2[2] + v2.w;
    float t1 = l1[3], t2 = l2[3];
    unsigned lane = tid & 31;
    int wid = tid >> 5;
    float s1 = t1, s2 = t2;
#pragma unroll
    for (int o = 1; o < 32; o <<= 1) {
        float a = __shfl_up_sync(0xffffffffu, s1, o);
        float b = __shfl_up_sync(0xffffffffu, s2, o);
        if (lane >= (unsigned)o) { s1 += a; s2 += b; }
    }
    if (lane == 31) { w1[wid] = s1; w2[wid] = s2; }
    __syncthreads();
    if (wid == 0) {
        float a1 = w1[lane], a2 = w2[lane];
        float b1 = a1, b2 = a2;
#pragma unroll
        for (int o = 1; o < 32; o <<= 1) {
            float x1 = __shfl_up_sync(0xffffffffu, b1, o);
            float x2 = __shfl_up_sync(0xffffffffu, b2, o);
            if (lane >= (unsigned)o) { b1 += x1; b2 += x2; }
        }
        w1[lane] = b1 - a1;
        w2[lane] = b2 - a2;
    }
    __syncthreads();
    float e1 = w1[wid] + s1 - t1;
    float e2 = w2[wid] + s2 - t2;
    int base = tid * 4;
#pragma unroll
    for (int e = 0; e < 4; e++) {
        c1[IDX(base + 1 + e)] = e1 + l1[e];
        c2[IDX(base + 1 + e)] = e2 + l2[e];
    }
    if (tid == 0) { c1[IDX(0)] = 0.0f; c2[IDX(0)] = 0.0f; }
    __syncthreads();
    float x01 = c1[IDX(1)], xl1 = c1[IDX(NN)] - c1[IDX(NN - 1)];
    float x02 = c2[IDX(1)], xl2 = c2[IDX(NN)] - c2[IDX(NN - 1)];
    float4 o1, o2;
#pragma unroll
    for (int e = 0; e < 4; e++) {
        int j = base + e;
        int hi = j + 50; if (hi > NN) hi = NN;
        int lo = j - 48; if (lo < 0) lo = 0;
        float lp = (float)(48 - j > 0 ? 48 - j : 0);
        float rp = (float)(j - 4046 > 0 ? j - 4046 : 0);
        ((float*)&o1)[e] = c1[IDX(hi)] - c1[IDX(lo)] + lp * x01 + rp * xl1;
        ((float*)&o2)[e] = c2[IDX(hi)] - c2[IDX(lo)] + lp * x02 + rp * xl2;
    }
    out1[(size_t)row * NG + tid] = o1;
    out2[(size_t)row * NG + tid] = o2;
}

// --- K5: vertical box of H1,H2 -> A, bb (running window, float4) ---
__global__ void k_vbox1_4() {
    int g = blockIdx.x * blockDim.x + threadIdx.x;
    int i0 = blockIdx.y * VCH;
    float4 s1 = f4zero(), s2 = f4zero();
#pragma unroll 4
    for (int k = i0 - 48; k <= i0 + 49; k++) {
        int kk = k < 0 ? 0 : (k > MM - 1 ? MM - 1 : k);
        s1 = f4add(s1, g_H1[(size_t)kk * NG + g]);
        s2 = f4add(s2, g_H2[(size_t)kk * NG + g]);
    }
    for (int ii = 0; ii < VCH; ii++) {
        int i = i0 + ii;
        float4 a, bb;
#pragma unroll
        for (int e = 0; e < 4; e++) {
            float m = ((float*)&s1)[e] * INVNORM;
            float m2 = ((float*)&s2)[e] * INVNORM;
            float var = m2 - m * m;
            float aa = __fdividef(var, var + 1.0f);
            ((float*)&a)[e] = aa;
            ((float*)&bb)[e] = m - aa * m;
        }
        g_A[(size_t)i * NG + g] = a;
        g_BB[(size_t)i * NG + g] = bb;
        if (ii < VCH - 1) {
            int ka = i + 50; if (ka > MM - 1) ka = MM - 1;
            int kr = i - 48; if (kr < 0) kr = 0;
            s1 = f4add(s1, f4sub(g_H1[(size_t)ka * NG + g], g_H1[(size_t)kr * NG + g]));
            s2 = f4add(s2, f4sub(g_H2[(size_t)ka * NG + g], g_H2[(size_t)kr * NG + g]));
        }
    }
}

// --- K7: vertical box of HA,Hbb -> diff + fused relu-rowdiff partial cumsum ---
__global__ void k_vbox2_4(const float4* __restrict__ ww, float4* __restrict__ out_diff) {
    int g = blockIdx.x * blockDim.x + threadIdx.x;
    int i0 = blockIdx.y * VCH;
    int istart = (i0 > 0) ? i0 - 1 : 0;
    float4 s1 = f4zero(), s2 = f4zero();
#pragma unroll 4
    for (int k = istart - 48; k <= istart + 49; k++) {
        int kk = k < 0 ? 0 : (k > MM - 1 ? MM - 1 : k);
        s1 = f4add(s1, g_H1[(size_t)kk * NG + g]);
        s2 = f4add(s2, g_H2[(size_t)kk * NG + g]);
    }
    float4 dprev = f4zero();
    if (i0 > 0) {
        float4 xv = g_X[(size_t)istart * NG + g];
        dprev = f4add(f4mul(f4muls(s1, INVNORM), xv), f4muls(s2, INVNORM));
        int ka = istart + 50; if (ka > MM - 1) ka = MM - 1;
        int kr = istart - 48; if (kr < 0) kr = 0;
        s1 = f4add(s1, f4sub(g_H1[(size_t)ka * NG + g], g_H1[(size_t)kr * NG + g]));
        s2 = f4add(s2, f4sub(g_H2[(size_t)ka * NG + g], g_H2[(size_t)kr * NG + g]));
    }
    float4 cum = f4zero();
    for (int ii = 0; ii < VCH; ii++) {
        int i = i0 + ii;
        float4 xv = g_X[(size_t)i * NG + g];
        float4 d = f4add(f4mul(f4muls(s1, INVNORM), xv), f4muls(s2, INVNORM));
        if (i > 0) {
            float4 wv = ww[(size_t)i * NG + g];
#pragma unroll
            for (int e = 0; e < 4; e++) {
                float delta = fmaxf(((float*)&d)[e] - ((float*)&dprev)[e], 0.0f) *
                              spf(((float*)&wv)[e]);
                ((float*)&cum)[e] += delta;
            }
        }
        out_diff[(size_t)i * NG + g] = d;
        g_PD[(size_t)i * NG + g] = cum;
        dprev = d;
        if (ii < VCH - 1) {
            int ka = i + 50; if (ka > MM - 1) ka = MM - 1;
            int kr = i - 48; if (kr < 0) kr = 0;
            s1 = f4add(s1, f4sub(g_H1[(size_t)ka * NG + g], g_H1[(size_t)kr * NG + g]));
            s2 = f4add(s2, f4sub(g_H2[(size_t)ka * NG + g], g_H2[(size_t)kr * NG + g]));
        }
    }
    g_PT[(size_t)blockIdx.y * NG + g] = cum;
}

// --- K9: finish outputs ---
__global__ void k_final4(float4* __restrict__ out_badpt, float4* __restrict__ out_da) {
    int t = blockIdx.x * blockDim.x + threadIdx.x;
    int i = t >> 10;
    int g = t & (NG - 1);
    float4 da = f4add(g_PD[t], g_OPD[((i >> 6) << 10) + g]);   // VCH=64
    out_da[t] = da;
    out_badpt[t] = f4sub(g_BADPT[t], da);
}

extern "C" void kernel_launch(void* const* d_in, const int* in_sizes, int n_in,
                              void* d_out, int out_size) {
    const float* f8[7] = {nullptr};
    const float* f3[2] = {nullptr};
    const float* hX = nullptr;
    int c8 = 0, c3 = 0;
    for (int i = 0; i < n_in; i++) {
        if (in_sizes[i] == MN && c8 < 7) f8[c8++] = (const float*)d_in[i];
        else if (in_sizes[i] == M3 * NN && c3 < 2) f3[c3++] = (const float*)d_in[i];
        else if (in_sizes[i] == 4 * MN) hX = (const float*)d_in[i];
    }
    const float4* b     = (const float4*)f8[0];
    const float4* fg    = (const float4*)f8[1];
    const float4* recon = (const float4*)f8[2];
    const float4* fm    = (const float4*)f8[3];
    const float4* bold  = (const float4*)f8[4];
    const float4* w     = (const float4*)f8[5];
    const float4* ww    = (const float4*)f8[6];
    const float4* bneg  = (const float4*)f3[0];
    const float4* dcol  = (const float4*)f3[1];
    const float4* hX4   = (const float4*)hX;

    float* out = (float*)d_out;
    float4* out_badpt = (float4*)out;
    float4* out_diff  = (float4*)(out + (size_t)MN);
    float4* out_da    = (float4*)(out + (size_t)2 * MN);
    float4* out_b     = (float4*)(out + (size_t)3 * MN);

    void *pCB, *pDC, *pCT, *pDT, *pOB, *pOD, *pPT, *pOPD, *pX, *pH1, *pH2, *pA, *pBB;
    cudaGetSymbolAddress(&pCB, g_CB);
    cudaGetSymbolAddress(&pDC, g_DC);
    cudaGetSymbolAddress(&pCT, g_CT);
    cudaGetSymbolAddress(&pDT, g_DT);
    cudaGetSymbolAddress(&pOB, g_OB);
    cudaGetSymbolAddress(&pOD, g_OD);
    cudaGetSymbolAddress(&pPT, g_PT);
    cudaGetSymbolAddress(&pOPD, g_OPD);
    cudaGetSymbolAddress(&pX, g_X);
    cudaGetSymbolAddress(&pH1, g_H1);
    cudaGetSymbolAddress(&pH2, g_H2);
    cudaGetSymbolAddress(&pA, g_A);
    cudaGetSymbolAddress(&pBB, g_BB);

    dim3 scanBlk(64, 4);
    k_colcumsum4<<<dim3(NG / 128, NCHB), 128>>>(b, w, (float4*)pCB, (float4*)pCT, MM);
    k_colcumsum4<<<dim3(NG / 128, NCHD), 128>>>(bneg, dcol, (float4*)pDC, (float4*)pDT, M3);
    k_scanpar<<<NG / 4, scanBlk>>>((const float4*)pCT, (float4*)pOB, NCHB);
    k_scanpar<<<NG / 4, scanBlk>>>((const float4*)pDT, (float4*)pOD, NCHD);
    // K3: fusion (separate streaming kernel)
    k_fusion4<<<(MN / 4) / 256, 256>>>(fg, fm, bold, hX4, recon, out_b);
    // K4: horizontal box of x, x^2 (1024-thread shape, skewed smem)
    k_hbox4<<<MM, 1024>>>((const float4*)pX, (const float4*)pX, (float4*)pH1, (float4*)pH2, 1);
    // K5: vertical box -> A, bb (VCH=64)
    k_vbox1_4<<<dim3(NG / 128, NVCH), 128>>>();
    // K6: horizontal box of A, bb
    k_hbox4<<<MM, 1024>>>((const float4*)pA, (const float4*)pBB, (float4*)pH1, (float4*)pH2, 0);
    // K7: vertical box -> diff + fused partial cumsum (VCH=64)
    k_vbox2_4<<<dim3(NG / 128, NVCH), 128>>>(ww, out_diff);
    k_scanpar<<<NG / 4, scanBlk>>>((const float4*)pPT, (float4*)pOPD, NVCH);
    k_final4<<<(MN / 4) / 256, 256>>>(out_badpt, out_da);
    (void)out_size;
}

// round 14
// speedup vs baseline: 1.3565x; 1.3565x over previous
#include <cuda_runtime.h>
#include <cstdint>

// stripe_post: m=2048, n=4096, m3=683, hX row-stride 4, GF r=49 eps=1
#define MM 2048
#define NN 4096
#define NG 1024             // float4 groups per row
#define NG2 2048            // float2 groups per row
#define M3 683
#define MN (MM * NN)
#define INVNORM (1.0f / 9604.0f)

#define CCH 32              // column-cumsum chunk rows
#define NCHB 64             // 2048/32
#define NCHD 22             // ceil(683/32)
#define VCH 32              // vertical box chunk rows (verified: more threads wins)
#define NVCH 64             // 2048/32

// skewed smem index: +1 float per 32 to spread banks (kills 4-way conflicts)
#define IDX(x) ((x) + ((x) >> 5))
#define CSZ (NN + 1 + ((NN + 1) >> 5) + 1)   // 4226

// scratch (static device arrays — allowed)
__device__ float4 g_CB[MN / 4];
__device__ float4 g_DC[(M3 * NN) / 4];
__device__ float4 g_CT[NCHB * NG];
__device__ float4 g_DT[NCHD * NG];
__device__ float4 g_OB[NCHB * NG];
__device__ float4 g_OD[NCHD * NG];
__device__ float4 g_BADPT[MN / 4];
__device__ float4 g_X[MN / 4];
__device__ float4 g_H1[MN / 4];
__device__ float4 g_H2[MN / 4];
__device__ float4 g_A[MN / 4];
__device__ float4 g_BB[MN / 4];
__device__ float4 g_PD[MN / 4];
__device__ float4 g_PT[NVCH * NG];
__device__ float4 g_OPD[NVCH * NG];

__device__ __forceinline__ float spf(float v) {
    return fmaxf(v, 0.0f) + __logf(1.0f + __expf(-fabsf(v)));
}
__device__ __forceinline__ float4 f4add(float4 a, float4 b) {
    return make_float4(a.x + b.x, a.y + b.y, a.z + b.z, a.w + b.w);
}
__device__ __forceinline__ float4 f4sub(float4 a, float4 b) {
    return make_float4(a.x - b.x, a.y - b.y, a.z - b.z, a.w - b.w);
}
__device__ __forceinline__ float4 f4mul(float4 a, float4 b) {
    return make_float4(a.x * b.x, a.y * b.y, a.z * b.z, a.w * b.w);
}
__device__ __forceinline__ float4 f4zero() { return make_float4(0.f, 0.f, 0.f, 0.f); }
__device__ __forceinline__ float4 f4lerp(float4 a, float4 b, float t) {
    return make_float4(a.x + (b.x - a.x) * t, a.y + (b.y - a.y) * t,
                       a.z + (b.z - a.z) * t, a.w + (b.w - a.w) * t);
}
__device__ __forceinline__ float4 f4sp(float4 a) {
    return make_float4(spf(a.x), spf(a.y), spf(a.z), spf(a.w));
}
__device__ __forceinline__ float2 f2add(float2 a, float2 b) {
    return make_float2(a.x + b.x, a.y + b.y);
}
__device__ __forceinline__ float2 f2sub(float2 a, float2 b) {
    return make_float2(a.x - b.x, a.y - b.y);
}
__device__ __forceinline__ float2 f2zero() { return make_float2(0.f, 0.f); }

// --- K1: within-chunk column cumsum of a*softplus(wgt), float4 lanes ---
__global__ void k_colcumsum4(const float4* __restrict__ a, const float4* __restrict__ wgt,
                             float4* __restrict__ out, float4* __restrict__ tot, int rows) {
    int g = blockIdx.x * blockDim.x + threadIdx.x;
    int start = blockIdx.y * CCH;
    int end = start + CCH;
    if (end > rows) end = rows;
    float4 cum = f4zero();
    for (int i = start; i < end; i++) {
        float4 av = a[(size_t)i * NG + g];
        float4 wv = wgt[(size_t)i * NG + g];
        cum = f4add(cum, f4mul(av, f4sp(wv)));
        out[(size_t)i * NG + g] = cum;
    }
    tot[(size_t)blockIdx.y * NG + g] = cum;
}

// --- K2: PARALLEL exclusive scan of chunk totals across chunks ---
__global__ void k_scanpar(const float4* __restrict__ tot, float4* __restrict__ off, int nch) {
    __shared__ float4 htot[4];
    int c = threadIdx.x;         // 0..63
    int l = threadIdx.y;         // 0..3
    int g = blockIdx.x * 4 + l;
    float4 v = (c < nch) ? tot[(size_t)c * NG + g] : f4zero();
    float4 s = v;
    unsigned lane = c & 31;
#pragma unroll
    for (int o = 1; o < 32; o <<= 1) {
        float4 t;
        t.x = __shfl_up_sync(0xffffffffu, s.x, o);
        t.y = __shfl_up_sync(0xffffffffu, s.y, o);
        t.z = __shfl_up_sync(0xffffffffu, s.z, o);
        t.w = __shfl_up_sync(0xffffffffu, s.w, o);
        if (lane >= (unsigned)o) s = f4add(s, t);
    }
    if (c == 31) htot[l] = s;
    __syncthreads();
    float4 e = f4sub(s, v);
    if (c >= 32) e = f4add(e, htot[l]);
    if (c < nch) off[(size_t)c * NG + g] = e;
}

// --- K3: fusion (resize decay, b, b_adpt, x) — pure streaming, high MLP ---
__global__ void k_fusion4(const float4* __restrict__ fg, const float4* __restrict__ fm,
                          const float4* __restrict__ bold, const float4* __restrict__ hX,
                          const float4* __restrict__ recon, float4* __restrict__ out_b) {
    int t = blockIdx.x * blockDim.x + threadIdx.x;
    int i = t >> 10;
    int g = t & (NG - 1);
    float4 bcs = f4add(g_CB[t], g_OB[((i >> 5) << 10) + g]);
    float sf = (i + 0.5f) * (683.0f / 2048.0f) - 0.5f;
    sf = fminf(fmaxf(sf, 0.0f), 682.0f);
    int i0 = (int)sf;
    float fr = sf - (float)i0;
    int i1 = i0 + 1; if (i1 > 682) i1 = 682;
    float4 d0 = f4add(g_DC[(size_t)i0 * NG + g], g_OD[((i0 >> 5) << 10) + g]);
    float4 d1 = f4add(g_DC[(size_t)i1 * NG + g], g_OD[((i1 >> 5) << 10) + g]);
    float4 dec = f4lerp(d0, d1, fr);
    float4 fgv = fg[t], fmv = fm[t], bo = bold[t], rc = recon[t];
    float4 bf = make_float4(bcs.x + dec.x * (1.0f - fgv.x), bcs.y + dec.y * (1.0f - fgv.y),
                            bcs.z + dec.z * (1.0f - fgv.z), bcs.w + dec.w * (1.0f - fgv.w));
    float4 ba = make_float4(bf.x * fmv.x + bo.x * (1.0f - fmv.x),
                            bf.y * fmv.y + bo.y * (1.0f - fmv.y),
                            bf.z * fmv.z + bo.z * (1.0f - fmv.z),
                            bf.w * fmv.w + bo.w * (1.0f - fmv.w));
    float4 hx = hX[(size_t)(i * 4) * NG + g];
    out_b[t] = bf;
    g_BADPT[t] = ba;
    g_X[t] = f4sub(f4add(hx, ba), rc);
}

// --- K4/K6: horizontal box via unpadded float4 prefix scan + edge corrections ---
// window s in [j-48, j+49] clamped (replicate):
//  box[j] = P[min(j+50,N)] - P[max(j-48,0)] + max(0,48-j)*x0 + max(0,j-4046)*xN
// smem prefix arrays use skewed indexing IDX() for conflict-free access.
__global__ __launch_bounds__(1024) void k_hbox4(const float4* __restrict__ in1,
                                                const float4* __restrict__ in2,
                                                float4* __restrict__ out1,
                                                float4* __restrict__ out2,
                                                int useSquare) {
    __shared__ float c1[CSZ];
    __shared__ float c2[CSZ];
    __shared__ float w1[32], w2[32];
    const int row = blockIdx.x;
    const int tid = threadIdx.x;
    float4 v1 = in1[(size_t)row * NG + tid];
    float4 v2 = useSquare ? f4mul(v1, v1) : in2[(size_t)row * NG + tid];
    float l1[4], l2[4];
    l1[0] = v1.x; l1[1] = l1[0] + v1.y; l1[2] = l1[1] + v1.z; l1[3] = l1[2] + v1.w;
    l2[0] = v2.x; l2[1] = l2[0] + v2.y; l2[2] = l2[1] + v2.z; l2[3] = l2[2] + v2.w;
    float t1 = l1[3], t2 = l2[3];
    unsigned lane = tid & 31;
    int wid = tid >> 5;
    float s1 = t1, s2 = t2;
#pragma unroll
    for (int o = 1; o < 32; o <<= 1) {
        float a = __shfl_up_sync(0xffffffffu, s1, o);
        float b = __shfl_up_sync(0xffffffffu, s2, o);
        if (lane >= (unsigned)o) { s1 += a; s2 += b; }
    }
    if (lane == 31) { w1[wid] = s1; w2[wid] = s2; }
    __syncthreads();
    if (wid == 0) {
        float a1 = w1[lane], a2 = w2[lane];
        float b1 = a1, b2 = a2;
#pragma unroll
        for (int o = 1; o < 32; o <<= 1) {
            float x1 = __shfl_up_sync(0xffffffffu, b1, o);
            float x2 = __shfl_up_sync(0xffffffffu, b2, o);
            if (lane >= (unsigned)o) { b1 += x1; b2 += x2; }
        }
        w1[lane] = b1 - a1;
        w2[lane] = b2 - a2;
    }
    __syncthreads();
    float e1 = w1[wid] + s1 - t1;
    float e2 = w2[wid] + s2 - t2;
    int base = tid * 4;
#pragma unroll
    for (int e = 0; e < 4; e++) {
        c1[IDX(base + 1 + e)] = e1 + l1[e];
        c2[IDX(base + 1 + e)] = e2 + l2[e];
    }
    if (tid == 0) { c1[IDX(0)] = 0.0f; c2[IDX(0)] = 0.0f; }
    __syncthreads();
    float x01 = c1[IDX(1)], xl1 = c1[IDX(NN)] - c1[IDX(NN - 1)];
    float x02 = c2[IDX(1)], xl2 = c2[IDX(NN)] - c2[IDX(NN - 1)];
    float4 o1, o2;
#pragma unroll
    for (int e = 0; e < 4; e++) {
        int j = base + e;
        int hi = j + 50; if (hi > NN) hi = NN;
        int lo = j - 48; if (lo < 0) lo = 0;
        float lp = (float)(48 - j > 0 ? 48 - j : 0);
        float rp = (float)(j - 4046 > 0 ? j - 4046 : 0);
        ((float*)&o1)[e] = c1[IDX(hi)] - c1[IDX(lo)] + lp * x01 + rp * xl1;
        ((float*)&o2)[e] = c2[IDX(hi)] - c2[IDX(lo)] + lp * x02 + rp * xl2;
    }
    out1[(size_t)row * NG + tid] = o1;
    out2[(size_t)row * NG + tid] = o2;
}

// --- K5: vertical box of H1,H2 -> A, bb — float2 lanes (2x threads, same traffic) ---
__global__ void k_vbox1_2() {
    const float2* H1 = (const float2*)g_H1;
    const float2* H2 = (const float2*)g_H2;
    float2* A = (float2*)g_A;
    float2* BB = (float2*)g_BB;
    int g = blockIdx.x * blockDim.x + threadIdx.x;   // 0..2047
    int i0 = blockIdx.y * VCH;
    float2 s1 = f2zero(), s2 = f2zero();
#pragma unroll 4
    for (int k = i0 - 48; k <= i0 + 49; k++) {
        int kk = k < 0 ? 0 : (k > MM - 1 ? MM - 1 : k);
        s1 = f2add(s1, H1[(size_t)kk * NG2 + g]);
        s2 = f2add(s2, H2[(size_t)kk * NG2 + g]);
    }
    for (int ii = 0; ii < VCH; ii++) {
        int i = i0 + ii;
        float2 a, bb;
#pragma unroll
        for (int e = 0; e < 2; e++) {
            float m = ((float*)&s1)[e] * INVNORM;
            float m2 = ((float*)&s2)[e] * INVNORM;
            float var = m2 - m * m;
            float aa = __fdividef(var, var + 1.0f);
            ((float*)&a)[e] = aa;
            ((float*)&bb)[e] = m - aa * m;
        }
        A[(size_t)i * NG2 + g] = a;
        BB[(size_t)i * NG2 + g] = bb;
        if (ii < VCH - 1) {
            int ka = i + 50; if (ka > MM - 1) ka = MM - 1;
            int kr = i - 48; if (kr < 0) kr = 0;
            s1 = f2add(s1, f2sub(H1[(size_t)ka * NG2 + g], H1[(size_t)kr * NG2 + g]));
            s2 = f2add(s2, f2sub(H2[(size_t)ka * NG2 + g], H2[(size_t)kr * NG2 + g]));
        }
    }
}

// --- K7: vertical box of HA,Hbb -> diff + fused relu-rowdiff partial cumsum (float2) ---
__global__ void k_vbox2_2(const float2* __restrict__ ww, float2* __restrict__ out_diff) {
    const float2* H1 = (const float2*)g_H1;
    const float2* H2 = (const float2*)g_H2;
    const float2* X = (const float2*)g_X;
    float2* PD = (float2*)g_PD;
    float2* PT = (float2*)g_PT;
    int g = blockIdx.x * blockDim.x + threadIdx.x;   // 0..2047
    int i0 = blockIdx.y * VCH;
    int istart = (i0 > 0) ? i0 - 1 : 0;
    float2 s1 = f2zero(), s2 = f2zero();
#pragma unroll 4
    for (int k = istart - 48; k <= istart + 49; k++) {
        int kk = k < 0 ? 0 : (k > MM - 1 ? MM - 1 : k);
        s1 = f2add(s1, H1[(size_t)kk * NG2 + g]);
        s2 = f2add(s2, H2[(size_t)kk * NG2 + g]);
    }
    float2 dprev = f2zero();
    if (i0 > 0) {
        float2 xv = X[(size_t)istart * NG2 + g];
        dprev = make_float2(s1.x * INVNORM * xv.x + s2.x * INVNORM,
                            s1.y * INVNORM * xv.y + s2.y * INVNORM);
        int ka = istart + 50; if (ka > MM - 1) ka = MM - 1;
        int kr = istart - 48; if (kr < 0) kr = 0;
        s1 = f2add(s1, f2sub(H1[(size_t)ka * NG2 + g], H1[(size_t)kr * NG2 + g]));
        s2 = f2add(s2, f2sub(H2[(size_t)ka * NG2 + g], H2[(size_t)kr * NG2 + g]));
    }
    float2 cum = f2zero();
    for (int ii = 0; ii < VCH; ii++) {
        int i = i0 + ii;
        float2 xv = X[(size_t)i * NG2 + g];
        float2 d = make_float2(s1.x * INVNORM * xv.x + s2.x * INVNORM,
                               s1.y * INVNORM * xv.y + s2.y * INVNORM);
        if (i > 0) {
            float2 wv = ww[(size_t)i * NG2 + g];
            cum.x += fmaxf(d.x - dprev.x, 0.0f) * spf(wv.x);
            cum.y += fmaxf(d.y - dprev.y, 0.0f) * spf(wv.y);
        }
        out_diff[(size_t)i * NG2 + g] = d;
        PD[(size_t)i * NG2 + g] = cum;
        dprev = d;
        if (ii < VCH - 1) {
            int ka = i + 50; if (ka > MM - 1) ka = MM - 1;
            int kr = i - 48; if (kr < 0) kr = 0;
            s1 = f2add(s1, f2sub(H1[(size_t)ka * NG2 + g], H1[(size_t)kr * NG2 + g]));
            s2 = f2add(s2, f2sub(H2[(size_t)ka * NG2 + g], H2[(size_t)kr * NG2 + g]));
        }
    }
    PT[(size_t)blockIdx.y * NG2 + g] = cum;   // same byte layout as float4 [c][NG]
}

// --- K9: finish outputs ---
__global__ void k_final4(float4* __restrict__ out_badpt, float4* __restrict__ out_da) {
    int t = blockIdx.x * blockDim.x + threadIdx.x;
    int i = t >> 10;
    int g = t & (NG - 1);
    float4 da = f4add(g_PD[t], g_OPD[((i >> 5) << 10) + g]);   // VCH=32
    out_da[t] = da;
    out_badpt[t] = f4sub(g_BADPT[t], da);
}

extern "C" void kernel_launch(void* const* d_in, const int* in_sizes, int n_in,
                              void* d_out, int out_size) {
    const float* f8[7] = {nullptr};
    const float* f3[2] = {nullptr};
    const float* hX = nullptr;
    int c8 = 0, c3 = 0;
    for (int i = 0; i < n_in; i++) {
        if (in_sizes[i] == MN && c8 < 7) f8[c8++] = (const float*)d_in[i];
        else if (in_sizes[i] == M3 * NN && c3 < 2) f3[c3++] = (const float*)d_in[i];
        else if (in_sizes[i] == 4 * MN) hX = (const float*)d_in[i];
    }
    const float4* b     = (const float4*)f8[0];
    const float4* fg    = (const float4*)f8[1];
    const float4* recon = (const float4*)f8[2];
    const float4* fm    = (const float4*)f8[3];
    const float4* bold  = (const float4*)f8[4];
    const float4* w     = (const float4*)f8[5];
    const float2* ww2   = (const float2*)f8[6];
    const float4* bneg  = (const float4*)f3[0];
    const float4* dcol  = (const float4*)f3[1];
    const float4* hX4   = (const float4*)hX;

    float* out = (float*)d_out;
    float4* out_badpt = (float4*)out;
    float2* out_diff2 = (float2*)(out + (size_t)MN);
    float4* out_da    = (float4*)(out + (size_t)2 * MN);
    float4* out_b     = (float4*)(out + (size_t)3 * MN);

    void *pCB, *pDC, *pCT, *pDT, *pOB, *pOD, *pPT, *pOPD, *pX, *pH1, *pH2, *pA, *pBB;
    cudaGetSymbolAddress(&pCB, g_CB);
    cudaGetSymbolAddress(&pDC, g_DC);
    cudaGetSymbolAddress(&pCT, g_CT);
    cudaGetSymbolAddress(&pDT, g_DT);
    cudaGetSymbolAddress(&pOB, g_OB);
    cudaGetSymbolAddress(&pOD, g_OD);
    cudaGetSymbolAddress(&pPT, g_PT);
    cudaGetSymbolAddress(&pOPD, g_OPD);
    cudaGetSymbolAddress(&pX, g_X);
    cudaGetSymbolAddress(&pH1, g_H1);
    cudaGetSymbolAddress(&pH2, g_H2);
    cudaGetSymbolAddress(&pA, g_A);
    cudaGetSymbolAddress(&pBB, g_BB);

    dim3 scanBlk(64, 4);
    k_colcumsum4<<<dim3(NG / 128, NCHB), 128>>>(b, w, (float4*)pCB, (float4*)pCT, MM);
    k_colcumsum4<<<dim3(NG / 128, NCHD), 128>>>(bneg, dcol, (float4*)pDC, (float4*)pDT, M3);
    k_scanpar<<<NG / 4, scanBlk>>>((const float4*)pCT, (float4*)pOB, NCHB);
    k_scanpar<<<NG / 4, scanBlk>>>((const float4*)pDT, (float4*)pOD, NCHD);
    // K3: fusion (separate streaming kernel)
    k_fusion4<<<(MN / 4) / 256, 256>>>(fg, fm, bold, hX4, recon, out_b);
    // K4: horizontal box of x, x^2 (1024-thread shape, skewed smem)
    k_hbox4<<<MM, 1024>>>((const float4*)pX, (const float4*)pX, (float4*)pH1, (float4*)pH2, 1);
    // K5: vertical box -> A, bb (float2 lanes: 128K threads, same traffic)
    k_vbox1_2<<<dim3(NG2 / 128, NVCH), 128>>>();
    // K6: horizontal box of A, bb
    k_hbox4<<<MM, 1024>>>((const float4*)pA, (const float4*)pBB, (float4*)pH1, (float4*)pH2, 0);
    // K7: vertical box -> diff + fused partial cumsum (float2 lanes)
    k_vbox2_2<<<dim3(NG2 / 128, NVCH), 128>>>(ww2, out_diff2);
    k_scanpar<<<NG / 4, scanBlk>>>((const float4*)pPT, (float4*)pOPD, NVCH);
    k_final4<<<(MN / 4) / 256, 256>>>(out_badpt, out_da);
    (void)out_size;
}

// round 16
// speedup vs baseline: 1.4564x; 1.0737x over previous
#include <cuda_runtime.h>
#include <cstdint>

// stripe_post: m=2048, n=4096, m3=683, hX row-stride 4, GF r=49 eps=1
#define MM 2048
#define NN 4096
#define NG 1024             // float4 groups per row
#define NG2 2048            // float2 groups per row
#define M3 683
#define MN (MM * NN)
#define INVNORM (1.0f / 9604.0f)

#define CCH 32              // column-cumsum chunk rows
#define NCHB 64             // 2048/32
#define NCHD 22             // ceil(683/32)
#define VCH 32              // vertical box chunk rows (verified: more threads wins)
#define NVCH 64             // 2048/32

// skewed smem index: +1 float per 32 to spread banks (kills 4-way conflicts)
#define IDX(x) ((x) + ((x) >> 5))
#define CSZ (NN + 1 + ((NN + 1) >> 5) + 1)   // 4226

// scratch (static device arrays — allowed)
__device__ float4 g_CB[MN / 4];
__device__ float4 g_DC[(M3 * NN) / 4];
__device__ float4 g_CT[NCHB * NG];
__device__ float4 g_DT[NCHD * NG];
__device__ float4 g_OB[NCHB * NG];
__device__ float4 g_OD[NCHD * NG];
__device__ float4 g_BADPT[MN / 4];
__device__ float4 g_X[MN / 4];
__device__ float4 g_H1[MN / 4];
__device__ float4 g_H2[MN / 4];
__device__ float4 g_A[MN / 4];
__device__ float4 g_BB[MN / 4];
__device__ float4 g_PD[MN / 4];
__device__ float4 g_PT[NVCH * NG];
__device__ float4 g_OPD[NVCH * NG];

__device__ __forceinline__ float spf(float v) {
    return fmaxf(v, 0.0f) + __logf(1.0f + __expf(-fabsf(v)));
}
__device__ __forceinline__ float4 f4add(float4 a, float4 b) {
    return make_float4(a.x + b.x, a.y + b.y, a.z + b.z, a.w + b.w);
}
__device__ __forceinline__ float4 f4sub(float4 a, float4 b) {
    return make_float4(a.x - b.x, a.y - b.y, a.z - b.z, a.w - b.w);
}
__device__ __forceinline__ float4 f4mul(float4 a, float4 b) {
    return make_float4(a.x * b.x, a.y * b.y, a.z * b.z, a.w * b.w);
}
__device__ __forceinline__ float4 f4zero() { return make_float4(0.f, 0.f, 0.f, 0.f); }
__device__ __forceinline__ float4 f4lerp(float4 a, float4 b, float t) {
    return make_float4(a.x + (b.x - a.x) * t, a.y + (b.y - a.y) * t,
                       a.z + (b.z - a.z) * t, a.w + (b.w - a.w) * t);
}
__device__ __forceinline__ float2 f2add(float2 a, float2 b) {
    return make_float2(a.x + b.x, a.y + b.y);
}
__device__ __forceinline__ float2 f2sub(float2 a, float2 b) {
    return make_float2(a.x - b.x, a.y - b.y);
}
__device__ __forceinline__ float2 f2zero() { return make_float2(0.f, 0.f); }

// --- K1: within-chunk column cumsum of a*softplus(wgt), float2 lanes (2x threads) ---
__global__ void k_colcumsum2(const float2* __restrict__ a, const float2* __restrict__ wgt,
                             float2* __restrict__ out, float2* __restrict__ tot, int rows) {
    int g = blockIdx.x * blockDim.x + threadIdx.x;   // 0..2047
    int start = blockIdx.y * CCH;
    int end = start + CCH;
    if (end > rows) end = rows;
    float2 cum = f2zero();
    for (int i = start; i < end; i++) {
        float2 av = a[(size_t)i * NG2 + g];
        float2 wv = wgt[(size_t)i * NG2 + g];
        cum.x += av.x * spf(wv.x);
        cum.y += av.y * spf(wv.y);
        out[(size_t)i * NG2 + g] = cum;
    }
    // float2 [c][NG2] layout is byte-identical to float4 [c][NG]
    tot[(size_t)blockIdx.y * NG2 + g] = cum;
}

// --- K2: PARALLEL exclusive scan of chunk totals across chunks ---
__global__ void k_scanpar(const float4* __restrict__ tot, float4* __restrict__ off, int nch) {
    __shared__ float4 htot[4];
    int c = threadIdx.x;         // 0..63
    int l = threadIdx.y;         // 0..3
    int g = blockIdx.x * 4 + l;
    float4 v = (c < nch) ? tot[(size_t)c * NG + g] : f4zero();
    float4 s = v;
    unsigned lane = c & 31;
#pragma unroll
    for (int o = 1; o < 32; o <<= 1) {
        float4 t;
        t.x = __shfl_up_sync(0xffffffffu, s.x, o);
        t.y = __shfl_up_sync(0xffffffffu, s.y, o);
        t.z = __shfl_up_sync(0xffffffffu, s.z, o);
        t.w = __shfl_up_sync(0xffffffffu, s.w, o);
        if (lane >= (unsigned)o) s = f4add(s, t);
    }
    if (c == 31) htot[l] = s;
    __syncthreads();
    float4 e = f4sub(s, v);
    if (c >= 32) e = f4add(e, htot[l]);
    if (c < nch) off[(size_t)c * NG + g] = e;
}

// --- K3: fusion (resize decay, b, b_adpt, x) — pure streaming, high MLP ---
__global__ void k_fusion4(const float4* __restrict__ fg, const float4* __restrict__ fm,
                          const float4* __restrict__ bold, const float4* __restrict__ hX,
                          const float4* __restrict__ recon, float4* __restrict__ out_b) {
    int t = blockIdx.x * blockDim.x + threadIdx.x;
    int i = t >> 10;
    int g = t & (NG - 1);
    float4 bcs = f4add(g_CB[t], g_OB[((i >> 5) << 10) + g]);
    float sf = (i + 0.5f) * (683.0f / 2048.0f) - 0.5f;
    sf = fminf(fmaxf(sf, 0.0f), 682.0f);
    int i0 = (int)sf;
    float fr = sf - (float)i0;
    int i1 = i0 + 1; if (i1 > 682) i1 = 682;
    float4 d0 = f4add(g_DC[(size_t)i0 * NG + g], g_OD[((i0 >> 5) << 10) + g]);
    float4 d1 = f4add(g_DC[(size_t)i1 * NG + g], g_OD[((i1 >> 5) << 10) + g]);
    float4 dec = f4lerp(d0, d1, fr);
    float4 fgv = fg[t], fmv = fm[t], bo = bold[t], rc = recon[t];
    float4 bf = make_float4(bcs.x + dec.x * (1.0f - fgv.x), bcs.y + dec.y * (1.0f - fgv.y),
                            bcs.z + dec.z * (1.0f - fgv.z), bcs.w + dec.w * (1.0f - fgv.w));
    float4 ba = make_float4(bf.x * fmv.x + bo.x * (1.0f - fmv.x),
                            bf.y * fmv.y + bo.y * (1.0f - fmv.y),
                            bf.z * fmv.z + bo.z * (1.0f - fmv.z),
                            bf.w * fmv.w + bo.w * (1.0f - fmv.w));
    float4 hx = hX[(size_t)(i * 4) * NG + g];
    out_b[t] = bf;
    g_BADPT[t] = ba;
    g_X[t] = f4sub(f4add(hx, ba), rc);
}

// --- K4/K6: horizontal box via unpadded float4 prefix scan + edge corrections ---
// window s in [j-48, j+49] clamped (replicate):
//  box[j] = P[min(j+50,N)] - P[max(j-48,0)] + max(0,48-j)*x0 + max(0,j-4046)*xN
// smem prefix arrays use skewed indexing IDX() for conflict-free access.
__global__ __launch_bounds__(1024) void k_hbox4(const float4* __restrict__ in1,
                                                const float4* __restrict__ in2,
                                                float4* __restrict__ out1,
                                                float4* __restrict__ out2,
                                                int useSquare) {
    __shared__ float c1[CSZ];
    __shared__ float c2[CSZ];
    __shared__ float w1[32], w2[32];
    const int row = blockIdx.x;
    const int tid = threadIdx.x;
    float4 v1 = in1[(size_t)row * NG + tid];
    float4 v2 = useSquare ? f4mul(v1, v1) : in2[(size_t)row * NG + tid];
    float l1[4], l2[4];
    l1[0] = v1.x; l1[1] = l1[0] + v1.y; l1[2] = l1[1] + v1.z; l1[3] = l1[2] + v1.w;
    l2[0] = v2.x; l2[1] = l2[0] + v2.y; l2[2] = l2[1] + v2.z; l2[3] = l2[2] + v2.w;
    float t1 = l1[3], t2 = l2[3];
    unsigned lane = tid & 31;
    int wid = tid >> 5;
    float s1 = t1, s2 = t2;
#pragma unroll
    for (int o = 1; o < 32; o <<= 1) {
        float a = __shfl_up_sync(0xffffffffu, s1, o);
        float b = __shfl_up_sync(0xffffffffu, s2, o);
        if (lane >= (unsigned)o) { s1 += a; s2 += b; }
    }
    if (lane == 31) { w1[wid] = s1; w2[wid] = s2; }
    __syncthreads();
    if (wid == 0) {
        float a1 = w1[lane], a2 = w2[lane];
        float b1 = a1, b2 = a2;
#pragma unroll
        for (int o = 1; o < 32; o <<= 1) {
            float x1 = __shfl_up_sync(0xffffffffu, b1, o);
            float x2 = __shfl_up_sync(0xffffffffu, b2, o);
            if (lane >= (unsigned)o) { b1 += x1; b2 += x2; }
        }
        w1[lane] = b1 - a1;
        w2[lane] = b2 - a2;
    }
    __syncthreads();
    float e1 = w1[wid] + s1 - t1;
    float e2 = w2[wid] + s2 - t2;
    int base = tid * 4;
#pragma unroll
    for (int e = 0; e < 4; e++) {
        c1[IDX(base + 1 + e)] = e1 + l1[e];
        c2[IDX(base + 1 + e)] = e2 + l2[e];
    }
    if (tid == 0) { c1[IDX(0)] = 0.0f; c2[IDX(0)] = 0.0f; }
    __syncthreads();
    float x01 = c1[IDX(1)], xl1 = c1[IDX(NN)] - c1[IDX(NN - 1)];
    float x02 = c2[IDX(1)], xl2 = c2[IDX(NN)] - c2[IDX(NN - 1)];
    float4 o1, o2;
#pragma unroll
    for (int e = 0; e < 4; e++) {
        int j = base + e;
        int hi = j + 50; if (hi > NN) hi = NN;
        int lo = j - 48; if (lo < 0) lo = 0;
        float lp = (float)(48 - j > 0 ? 48 - j : 0);
        float rp = (float)(j - 4046 > 0 ? j - 4046 : 0);
        ((float*)&o1)[e] = c1[IDX(hi)] - c1[IDX(lo)] + lp * x01 + rp * xl1;
        ((float*)&o2)[e] = c2[IDX(hi)] - c2[IDX(lo)] + lp * x02 + rp * xl2;
    }
    out1[(size_t)row * NG + tid] = o1;
    out2[(size_t)row * NG + tid] = o2;
}

// --- K5: vertical box of H1,H2 -> A, bb — float2 lanes (2x threads, same traffic) ---
__global__ void k_vbox1_2() {
    const float2* H1 = (const float2*)g_H1;
    const float2* H2 = (const float2*)g_H2;
    float2* A = (float2*)g_A;
    float2* BB = (float2*)g_BB;
    int g = blockIdx.x * blockDim.x + threadIdx.x;   // 0..2047
    int i0 = blockIdx.y * VCH;
    float2 s1 = f2zero(), s2 = f2zero();
#pragma unroll 4
    for (int k = i0 - 48; k <= i0 + 49; k++) {
        int kk = k < 0 ? 0 : (k > MM - 1 ? MM - 1 : k);
        s1 = f2add(s1, H1[(size_t)kk * NG2 + g]);
        s2 = f2add(s2, H2[(size_t)kk * NG2 + g]);
    }
    for (int ii = 0; ii < VCH; ii++) {
        int i = i0 + ii;
        float2 a, bb;
#pragma unroll
        for (int e = 0; e < 2; e++) {
            float m = ((float*)&s1)[e] * INVNORM;
            float m2 = ((float*)&s2)[e] * INVNORM;
            float var = m2 - m * m;
            float aa = __fdividef(var, var + 1.0f);
            ((float*)&a)[e] = aa;
            ((float*)&bb)[e] = m - aa * m;
        }
        A[(size_t)i * NG2 + g] = a;
        BB[(size_t)i * NG2 + g] = bb;
        if (ii < VCH - 1) {
            int ka = i + 50; if (ka > MM - 1) ka = MM - 1;
            int kr = i - 48; if (kr < 0) kr = 0;
            s1 = f2add(s1, f2sub(H1[(size_t)ka * NG2 + g], H1[(size_t)kr * NG2 + g]));
            s2 = f2add(s2, f2sub(H2[(size_t)ka * NG2 + g], H2[(size_t)kr * NG2 + g]));
        }
    }
}

// --- K7: vertical box of HA,Hbb -> diff + fused relu-rowdiff partial cumsum (float2) ---
__global__ void k_vbox2_2(const float2* __restrict__ ww, float2* __restrict__ out_diff) {
    const float2* H1 = (const float2*)g_H1;
    const float2* H2 = (const float2*)g_H2;
    const float2* X = (const float2*)g_X;
    float2* PD = (float2*)g_PD;
    float2* PT = (float2*)g_PT;
    int g = blockIdx.x * blockDim.x + threadIdx.x;   // 0..2047
    int i0 = blockIdx.y * VCH;
    int istart = (i0 > 0) ? i0 - 1 : 0;
    float2 s1 = f2zero(), s2 = f2zero();
#pragma unroll 4
    for (int k = istart - 48; k <= istart + 49; k++) {
        int kk = k < 0 ? 0 : (k > MM - 1 ? MM - 1 : k);
        s1 = f2add(s1, H1[(size_t)kk * NG2 + g]);
        s2 = f2add(s2, H2[(size_t)kk * NG2 + g]);
    }
    float2 dprev = f2zero();
    if (i0 > 0) {
        float2 xv = X[(size_t)istart * NG2 + g];
        dprev = make_float2(s1.x * INVNORM * xv.x + s2.x * INVNORM,
                            s1.y * INVNORM * xv.y + s2.y * INVNORM);
        int ka = istart + 50; if (ka > MM - 1) ka = MM - 1;
        int kr = istart - 48; if (kr < 0) kr = 0;
        s1 = f2add(s1, f2sub(H1[(size_t)ka * NG2 + g], H1[(size_t)kr * NG2 + g]));
        s2 = f2add(s2, f2sub(H2[(size_t)ka * NG2 + g], H2[(size_t)kr * NG2 + g]));
    }
    float2 cum = f2zero();
    for (int ii = 0; ii < VCH; ii++) {
        int i = i0 + ii;
        float2 xv = X[(size_t)i * NG2 + g];
        float2 d = make_float2(s1.x * INVNORM * xv.x + s2.x * INVNORM,
                               s1.y * INVNORM * xv.y + s2.y * INVNORM);
        if (i > 0) {
            float2 wv = ww[(size_t)i * NG2 + g];
            cum.x += fmaxf(d.x - dprev.x, 0.0f) * spf(wv.x);
            cum.y += fmaxf(d.y - dprev.y, 0.0f) * spf(wv.y);
        }
        out_diff[(size_t)i * NG2 + g] = d;
        PD[(size_t)i * NG2 + g] = cum;
        dprev = d;
        if (ii < VCH - 1) {
            int ka = i + 50; if (ka > MM - 1) ka = MM - 1;
            int kr = i - 48; if (kr < 0) kr = 0;
            s1 = f2add(s1, f2sub(H1[(size_t)ka * NG2 + g], H1[(size_t)kr * NG2 + g]));
            s2 = f2add(s2, f2sub(H2[(size_t)ka * NG2 + g], H2[(size_t)kr * NG2 + g]));
        }
    }
    PT[(size_t)blockIdx.y * NG2 + g] = cum;   // same byte layout as float4 [c][NG]
}

// --- K9: finish outputs ---
__global__ void k_final4(float4* __restrict__ out_badpt, float4* __restrict__ out_da) {
    int t = blockIdx.x * blockDim.x + threadIdx.x;
    int i = t >> 10;
    int g = t & (NG - 1);
    float4 da = f4add(g_PD[t], g_OPD[((i >> 5) << 10) + g]);   // VCH=32
    out_da[t] = da;
    out_badpt[t] = f4sub(g_BADPT[t], da);
}

extern "C" void kernel_launch(void* const* d_in, const int* in_sizes, int n_in,
                              void* d_out, int out_size) {
    const float* f8[7] = {nullptr};
    const float* f3[2] = {nullptr};
    const float* hX = nullptr;
    int c8 = 0, c3 = 0;
    for (int i = 0; i < n_in; i++) {
        if (in_sizes[i] == MN && c8 < 7) f8[c8++] = (const float*)d_in[i];
        else if (in_sizes[i] == M3 * NN && c3 < 2) f3[c3++] = (const float*)d_in[i];
        else if (in_sizes[i] == 4 * MN) hX = (const float*)d_in[i];
    }
    const float2* b2    = (const float2*)f8[0];
    const float4* fg    = (const float4*)f8[1];
    const float4* recon = (const float4*)f8[2];
    const float4* fm    = (const float4*)f8[3];
    const float4* bold  = (const float4*)f8[4];
    const float2* w2    = (const float2*)f8[5];
    const float2* ww2   = (const float2*)f8[6];
    const float2* bneg2 = (const float2*)f3[0];
    const float2* dcol2 = (const float2*)f3[1];
    const float4* hX4   = (const float4*)hX;

    float* out = (float*)d_out;
    float4* out_badpt = (float4*)out;
    float2* out_diff2 = (float2*)(out + (size_t)MN);
    float4* out_da    = (float4*)(out + (size_t)2 * MN);
    float4* out_b     = (float4*)(out + (size_t)3 * MN);

    void *pCB, *pDC, *pCT, *pDT, *pOB, *pOD, *pPT, *pOPD, *pX, *pH1, *pH2, *pA, *pBB;
    cudaGetSymbolAddress(&pCB, g_CB);
    cudaGetSymbolAddress(&pDC, g_DC);
    cudaGetSymbolAddress(&pCT, g_CT);
    cudaGetSymbolAddress(&pDT, g_DT);
    cudaGetSymbolAddress(&pOB, g_OB);
    cudaGetSymbolAddress(&pOD, g_OD);
    cudaGetSymbolAddress(&pPT, g_PT);
    cudaGetSymbolAddress(&pOPD, g_OPD);
    cudaGetSymbolAddress(&pX, g_X);
    cudaGetSymbolAddress(&pH1, g_H1);
    cudaGetSymbolAddress(&pH2, g_H2);
    cudaGetSymbolAddress(&pA, g_A);
    cudaGetSymbolAddress(&pBB, g_BB);

    dim3 scanBlk(64, 4);
    // K1: column cumsums, float2 lanes (2x threads, same traffic)
    k_colcumsum2<<<dim3(NG2 / 128, NCHB), 128>>>(b2, w2, (float2*)pCB, (float2*)pCT, MM);
    k_colcumsum2<<<dim3(NG2 / 128, NCHD), 128>>>(bneg2, dcol2, (float2*)pDC, (float2*)pDT, M3);
    k_scanpar<<<NG / 4, scanBlk>>>((const float4*)pCT, (float4*)pOB, NCHB);
    k_scanpar<<<NG / 4, scanBlk>>>((const float4*)pDT, (float4*)pOD, NCHD);
    // K3: fusion (separate streaming kernel)
    k_fusion4<<<(MN / 4) / 256, 256>>>(fg, fm, bold, hX4, recon, out_b);
    // K4: horizontal box of x, x^2 (1024-thread shape, skewed smem)
    k_hbox4<<<MM, 1024>>>((const float4*)pX, (const float4*)pX, (float4*)pH1, (float4*)pH2, 1);
    // K5: vertical box -> A, bb (float2 lanes)
    k_vbox1_2<<<dim3(NG2 / 128, NVCH), 128>>>();
    // K6: horizontal box of A, bb
    k_hbox4<<<MM, 1024>>>((const float4*)pA, (const float4*)pBB, (float4*)pH1, (float4*)pH2, 0);
    // K7: vertical box -> diff + fused partial cumsum (float2 lanes)
    k_vbox2_2<<<dim3(NG2 / 128, NVCH), 128>>>(ww2, out_diff2);
    k_scanpar<<<NG / 4, scanBlk>>>((const float4*)pPT, (float4*)pOPD, NVCH);
    k_final4<<<(MN / 4) / 256, 256>>>(out_badpt, out_da);
    (void)out_size;
}